// round 10
// baseline (speedup 1.0000x reference)
#include <cuda_runtime.h>
#include <cuda_fp16.h>
#include <math.h>
#include <stdint.h>

#define NB 512
#define NL 128
#define ND 256
#define NF 512
#define NE 8

// ---------------------------------------------------------------------------
// Device scratch (allocation-free rule)
// ---------------------------------------------------------------------------
__device__ float g_gates[NB * NE];
__device__ __half g_Xh[(size_t)NB * NL * ND];
__device__ __half g_W1T[(size_t)NE * NF * ND];   // [e][n][k]
__device__ __half g_W2T[(size_t)NE * ND * NF];   // [e][n][k]
__device__ __half g_H[(size_t)NB * NE * NL * NF];
__device__ unsigned g_ctr1;                      // gemm1 task counter
__device__ unsigned g_ctr2;                      // gemm2 task counter

#define GRID_PERSIST 296                         // 2 CTAs/SM x 148 SMs

// ---------------------------------------------------------------------------
// PTX helpers — baseline (non-'a') features only: cp.async, ldmatrix, mma.sync
// ---------------------------------------------------------------------------
__device__ __forceinline__ uint32_t smem_u32(const void* p) {
    uint32_t a;
    asm("{ .reg .u64 t; cvta.to.shared.u64 t, %1; cvt.u32.u64 %0, t; }" : "=r"(a) : "l"(p));
    return a;
}
__device__ __forceinline__ void cp16(uint32_t dst, const void* src) {
    asm volatile("cp.async.cg.shared.global [%0], [%1], 16;" :: "r"(dst), "l"(src));
}
#define CP_COMMIT() asm volatile("cp.async.commit_group;" ::: "memory")
#define CP_WAIT0()  asm volatile("cp.async.wait_group 0;" ::: "memory")
#define CP_WAIT1()  asm volatile("cp.async.wait_group 1;" ::: "memory")

#define LDSM4(r0, r1, r2, r3, addr) \
    asm volatile("ldmatrix.sync.aligned.m8n8.x4.shared.b16 {%0,%1,%2,%3}, [%4];" \
                 : "=r"(r0), "=r"(r1), "=r"(r2), "=r"(r3) : "r"(addr))

#define MMA16816(c, a, b0, b1) \
    asm volatile("mma.sync.aligned.m16n8k16.row.col.f32.f16.f16.f32 " \
                 "{%0,%1,%2,%3}, {%4,%5,%6,%7}, {%8,%9}, {%0,%1,%2,%3};" \
                 : "+f"((c)[0]), "+f"((c)[1]), "+f"((c)[2]), "+f"((c)[3]) \
                 : "r"((a)[0]), "r"((a)[1]), "r"((a)[2]), "r"((a)[3]), \
                   "r"(b0), "r"(b1))

__device__ __forceinline__ float gelu_exact(float v) {
    return 0.5f * v * (1.0f + erff(v * 0.70710678118654752f));
}

// ---------------------------------------------------------------------------
// Tile geometry
// ---------------------------------------------------------------------------
#define ROW_BYTES 144                               // streamed 64-col tiles
#define TILE_BYTES (128 * ROW_BYTES)                // 18432
// GEMM1 SMEM: X resident [128][264] f16 (stride 528B) + 2 B stages
#define X_STRIDE 528
#define G1_X 0
#define G1_B(st) (67584 + (st) * TILE_BYTES)
#define G1_SMEM (67584 + 2 * TILE_BYTES)            // 104448
// GEMM2 SMEM: 3 stages x (A+B)
#define STAGE_BYTES (2 * TILE_BYTES)                // 36864
#define SM_A(st) ((st) * STAGE_BYTES)
#define SM_B(st) ((st) * STAGE_BYTES + TILE_BYTES)
#define G2_SMEM (3 * STAGE_BYTES)                   // 110592

// Fill a [128 x 64] f16 tile (stride ROW_BYTES) via cp.async: 4 x 16B/thread.
__device__ __forceinline__ void fill_tile(uint32_t dst, const __half* src,
                                          int stride, int tid) {
#pragma unroll
    for (int i = 0; i < 4; i++) {
        int q = tid + i * 256;
        int r = q >> 3;
        int c = (q & 7) << 3;
        cp16(dst + r * ROW_BYTES + c * 2, src + (size_t)r * stride + c);
    }
}

// GEMM2-style compute: A and B both in streamed tiles.
__device__ __forceinline__ void compute_stage(uint32_t smb, int st, int wm, int wn,
                                              int lane, float acc[4][4][4]) {
#pragma unroll
    for (int ks = 0; ks < 4; ks++) {
        uint32_t a[4][4];
#pragma unroll
        for (int mi = 0; mi < 4; mi++) {
            uint32_t ad = smb + SM_A(st) +
                (wm * 64 + mi * 16 + (lane & 15)) * ROW_BYTES + ks * 32 + (lane >> 4) * 16;
            LDSM4(a[mi][0], a[mi][1], a[mi][2], a[mi][3], ad);
        }
        uint32_t bfr[2][4];
        int quad = lane >> 3;
#pragma unroll
        for (int g = 0; g < 2; g++) {
            uint32_t bd = smb + SM_B(st) +
                (wn * 32 + g * 16 + (quad >> 1) * 8 + (lane & 7)) * ROW_BYTES +
                ks * 32 + (quad & 1) * 16;
            LDSM4(bfr[g][0], bfr[g][1], bfr[g][2], bfr[g][3], bd);
        }
#pragma unroll
        for (int mi = 0; mi < 4; mi++)
#pragma unroll
            for (int ni = 0; ni < 4; ni++)
                MMA16816(acc[mi][ni], a[mi],
                         bfr[ni >> 1][(ni & 1) * 2], bfr[ni >> 1][(ni & 1) * 2 + 1]);
    }
}

// GEMM1 compute: A from resident X (stride 528B, chunk kc), B from streamed tile.
__device__ __forceinline__ void compute_xres(uint32_t smb, uint32_t bst, int kc,
                                             int wm, int wn, int lane,
                                             float acc[4][4][4]) {
#pragma unroll
    for (int ks = 0; ks < 4; ks++) {
        uint32_t a[4][4];
#pragma unroll
        for (int mi = 0; mi < 4; mi++) {
            uint32_t ad = smb + G1_X +
                (wm * 64 + mi * 16 + (lane & 15)) * X_STRIDE + kc * 128 + ks * 32 +
                (lane >> 4) * 16;
            LDSM4(a[mi][0], a[mi][1], a[mi][2], a[mi][3], ad);
        }
        uint32_t bfr[2][4];
        int quad = lane >> 3;
#pragma unroll
        for (int g = 0; g < 2; g++) {
            uint32_t bd = bst +
                (wn * 32 + g * 16 + (quad >> 1) * 8 + (lane & 7)) * ROW_BYTES +
                ks * 32 + (quad & 1) * 16;
            LDSM4(bfr[g][0], bfr[g][1], bfr[g][2], bfr[g][3], bd);
        }
#pragma unroll
        for (int mi = 0; mi < 4; mi++)
#pragma unroll
            for (int ni = 0; ni < 4; ni++)
                MMA16816(acc[mi][ni], a[mi],
                         bfr[ni >> 1][(ni & 1) * 2], bfr[ni >> 1][(ni & 1) * 2 + 1]);
    }
}

// ---------------------------------------------------------------------------
// Merged prep kernel: gates + X convert + W1/W2 transposes + counter reset.
// ---------------------------------------------------------------------------
#define PREP_GRID 10242

__global__ void prep_kernel(const float* __restrict__ x,
                            const float* __restrict__ W1,
                            const float* __restrict__ W2,
                            const float* __restrict__ logits,
                            const int* __restrict__ masks) {
    __shared__ float t[32][33];
    const int bid = blockIdx.x;
    if (bid < 8192) {
        size_t i0 = ((size_t)bid * 256 + threadIdx.x) * 8;
        float4 v0 = *(const float4*)(x + i0);
        float4 v1 = *(const float4*)(x + i0 + 4);
        __half2 h0 = __floats2half2_rn(v0.x, v0.y);
        __half2 h1 = __floats2half2_rn(v0.z, v0.w);
        __half2 h2 = __floats2half2_rn(v1.x, v1.y);
        __half2 h3 = __floats2half2_rn(v1.z, v1.w);
        uint4 u;
        u.x = *(uint32_t*)&h0; u.y = *(uint32_t*)&h1;
        u.z = *(uint32_t*)&h2; u.w = *(uint32_t*)&h3;
        *(uint4*)(g_Xh + i0) = u;
    } else if (bid < 9216) {
        int id = bid - 8192;                 // nt(16) x kt(8) x e(8)
        int nt = id & 15, kt = (id >> 4) & 7, e = id >> 7;
        int k0 = kt * 32, n0 = nt * 32;
        int r = threadIdx.x >> 5, c = threadIdx.x & 31;
#pragma unroll
        for (int i = 0; i < 4; i++)
            t[r + i * 8][c] = W1[((size_t)e * ND + k0 + r + i * 8) * NF + n0 + c];
        __syncthreads();
#pragma unroll
        for (int i = 0; i < 4; i++)
            g_W1T[((size_t)e * NF + n0 + r + i * 8) * ND + k0 + c] =
                __float2half(t[c][r + i * 8]);
    } else if (bid < 10240) {
        int id = bid - 9216;                 // nt(8) x kt(16) x e(8)
        int nt = id & 7, kt = (id >> 3) & 15, e = id >> 7;
        int k0 = kt * 32, n0 = nt * 32;
        int r = threadIdx.x >> 5, c = threadIdx.x & 31;
#pragma unroll
        for (int i = 0; i < 4; i++)
            t[r + i * 8][c] = W2[((size_t)e * NF + k0 + r + i * 8) * ND + n0 + c];
        __syncthreads();
#pragma unroll
        for (int i = 0; i < 4; i++)
            g_W2T[((size_t)e * ND + n0 + r + i * 8) * NF + k0 + c] =
                __float2half(t[c][r + i * 8]);
    } else {
        if (bid == 10240 && threadIdx.x == 0) { g_ctr1 = 0u; g_ctr2 = 0u; }
        int b = (bid - 10240) * 256 + threadIdx.x;
        if (b >= NB) return;
        float v[NE]; float mx = -1e30f;
#pragma unroll
        for (int e = 0; e < NE; e++) { v[e] = logits[b * NE + e]; mx = fmaxf(mx, v[e]); }
        float s = 0.f;
#pragma unroll
        for (int e = 0; e < NE; e++) { v[e] = expf(v[e] - mx); s += v[e]; }
        float inv = 1.f / s; float gs = 0.f;
#pragma unroll
        for (int e = 0; e < NE; e++) {
            v[e] = (masks[b * NE + e] == 1) ? v[e] * inv : 0.f;
            gs += v[e];
        }
        float d = 1.f / (gs + 1e-9f);
#pragma unroll
        for (int e = 0; e < NE; e++) g_gates[b * NE + e] = v[e] * d;
    }
}

// ---------------------------------------------------------------------------
// GEMM1 (persistent): CTAs pull (b,e) tasks from g_ctr1. Per active task:
// X[b] resident in SMEM; W1 B-tiles streamed (2-stage). For nt in 0..3:
// K=256 loop, epilogue H = gate*gelu(D + b1) -> fp16, SMEM-staged stores.
// ---------------------------------------------------------------------------
__global__ void __launch_bounds__(256, 2) gemm1_kernel(const float* __restrict__ b1) {
    extern __shared__ __align__(128) char sm[];
    __shared__ unsigned s_task;
    const uint32_t smb = smem_u32(sm);
    const int tid = threadIdx.x, lane = tid & 31, wid = tid >> 5;
    const int wm = wid & 1, wn = wid >> 1;

    for (;;) {
        if (tid == 0) s_task = atomicAdd(&g_ctr1, 1u);
        __syncthreads();
        const unsigned task = s_task;
        __syncthreads();
        if (task >= NB * NE) break;
        const int b = task >> 3, e = task & 7;
        const float gate = g_gates[b * NE + e];
        if (gate == 0.0f) continue;

        // Load X[b] (128 x 256 f16) into resident SMEM.
        {
            const __half* Xs = g_Xh + (size_t)b * NL * ND;
#pragma unroll
            for (int i = 0; i < 16; i++) {
                int q = tid + i * 256;          // 128 rows x 32 16B-chunks
                int r = q >> 5;
                int c = (q & 31) << 3;
                cp16(smb + G1_X + r * X_STRIDE + c * 2, Xs + (size_t)r * ND + c);
            }
            CP_COMMIT();
        }

        const __half* Bbase = g_W1T + (size_t)e * NF * ND;

        for (int nt = 0; nt < 4; nt++) {
            const __half* Bt = Bbase + (size_t)(nt * 128) * ND;
            fill_tile(G1_B(0) + smb, Bt, ND, tid); CP_COMMIT();
            fill_tile(G1_B(1) + smb, Bt + 64, ND, tid); CP_COMMIT();

            float acc[4][4][4] = {};
#pragma unroll
            for (int kc = 0; kc < 4; kc++) {
                if (kc < 3) { CP_WAIT1(); } else { CP_WAIT0(); }
                __syncthreads();
                compute_xres(smb, smb + G1_B(kc & 1), kc, wm, wn, lane, acc);
                __syncthreads();
                if (kc + 2 < 4) {
                    fill_tile(G1_B(kc & 1) + smb, Bt + (kc + 2) * 64, ND, tid);
                    CP_COMMIT();
                }
            }

            // Epilogue: stage gated-GELU fp16 tile (stride 272B) in B area,
            // then coalesced 16B global writes.
            const uint32_t sh = smb + G1_B(0);
            const int r0 = lane >> 2, c0 = (lane & 3) * 2;
#pragma unroll
            for (int mi = 0; mi < 4; mi++) {
#pragma unroll
                for (int ni = 0; ni < 4; ni++) {
                    int lc = wn * 32 + ni * 8 + c0;
                    float bb0 = __ldg(b1 + e * NF + nt * 128 + lc);
                    float bb1 = __ldg(b1 + e * NF + nt * 128 + lc + 1);
#pragma unroll
                    for (int h = 0; h < 2; h++) {
                        int row = wm * 64 + mi * 16 + r0 + h * 8;
                        float v0 = gate * gelu_exact(acc[mi][ni][h * 2 + 0] + bb0);
                        float v1 = gate * gelu_exact(acc[mi][ni][h * 2 + 1] + bb1);
                        __half h0 = __float2half(v0);
                        __half h1 = __float2half(v1);
                        uint32_t hp = (uint32_t)__half_as_ushort(h0) |
                                      ((uint32_t)__half_as_ushort(h1) << 16);
                        asm volatile("st.shared.b32 [%0], %1;"
                                     :: "r"(sh + row * 272 + lc * 2), "r"(hp));
                    }
                }
            }
            __syncthreads();

            __half* Hp = g_H + (size_t)(b * NE + e) * NL * NF + nt * 128;
#pragma unroll
            for (int it = 0; it < 8; it++) {
                int idx = tid + it * 256;       // 128 rows x 16 16B-units
                int row = idx >> 4;
                int u = idx & 15;
                float4 vh;
                asm volatile("ld.shared.v4.b32 {%0,%1,%2,%3}, [%4];"
                             : "=f"(vh.x), "=f"(vh.y), "=f"(vh.z), "=f"(vh.w)
                             : "r"(sh + row * 272 + u * 16));
                *(float4*)(Hp + (size_t)row * NF + u * 8) = vh;
            }
            __syncthreads();   // staging buffer reused by next nt's fills
        }
    }
}

// ---------------------------------------------------------------------------
// GEMM2 (persistent): CTAs pull (b,nt) tasks from g_ctr2. Per task:
// out = sum_{e active} H_e[128,512] @ W2T_e[.,512]^T + sum_e g_e*b2_e.
// 3-stage pipeline, one barrier per chunk (head barrier orders WAR).
// ---------------------------------------------------------------------------
__global__ void __launch_bounds__(256, 2) gemm2_kernel(const float* __restrict__ b2,
                                                       float* __restrict__ out) {
    extern __shared__ __align__(128) char sm[];
    __shared__ unsigned s_task;
    __shared__ float cb[128];
    const uint32_t smb = smem_u32(sm);
    const int tid = threadIdx.x, lane = tid & 31, wid = tid >> 5;
    const int wm = wid & 1, wn = wid >> 1;

    for (;;) {
        if (tid == 0) s_task = atomicAdd(&g_ctr2, 1u);
        __syncthreads();
        const unsigned task = s_task;
        __syncthreads();
        if (task >= NB * 2) break;
        const int b = task >> 1, nt = task & 1;
        const int n0 = nt * 128;

        float gates[NE];
        int act[NE], na = 0;
#pragma unroll
        for (int e = 0; e < NE; e++) {
            gates[e] = g_gates[b * NE + e];
            if (gates[e] != 0.0f) act[na++] = e;
        }
        if (na == 0) {
            float4 z = make_float4(0.f, 0.f, 0.f, 0.f);
            float* o = out + (size_t)b * NL * ND + n0;
            for (int i = tid; i < NL * 32; i += 256) {
                int r = i >> 5, c = (i & 31) << 2;
                *(float4*)(o + (size_t)r * ND + c) = z;
            }
            continue;
        }

        if (tid < 128) {
            float s = 0.f;
#pragma unroll
            for (int e = 0; e < NE; e++) s += gates[e] * __ldg(b2 + e * ND + n0 + tid);
            cb[tid] = s;
        }

        float acc[4][4][4] = {};
        const int total = na * 8;  // per expert: 8 BK=64 chunks over K=512

        auto srcs = [&](int i, const __half*& As, const __half*& Bs) {
            int e = act[i >> 3];
            int k = (i & 7) << 6;
            As = g_H + (size_t)(b * NE + e) * NL * NF + k;
            Bs = g_W2T + ((size_t)e * ND + n0) * NF + k;
        };

        {
            const __half *As, *Bs;
            srcs(0, As, Bs);
            fill_tile(smb + SM_A(0), As, NF, tid);
            fill_tile(smb + SM_B(0), Bs, NF, tid);
            CP_COMMIT();
            srcs(1, As, Bs);
            fill_tile(smb + SM_A(1), As, NF, tid);
            fill_tile(smb + SM_B(1), Bs, NF, tid);
            CP_COMMIT();
        }
        for (int i = 0; i < total; i++) {
            if (i + 1 < total) { CP_WAIT1(); } else { CP_WAIT0(); }
            __syncthreads();                     // single barrier per chunk
            if (i + 2 < total) {
                const __half *As, *Bs;
                srcs(i + 2, As, Bs);
                fill_tile(smb + SM_A((i + 2) % 3), As, NF, tid);
                fill_tile(smb + SM_B((i + 2) % 3), Bs, NF, tid);
                CP_COMMIT();
            }
            compute_stage(smb, i % 3, wm, wn, lane, acc);
        }

        // Epilogue: add gate-weighted bias, write fp32 out
        const int r0 = lane >> 2, c0 = (lane & 3) * 2;
#pragma unroll
        for (int mi = 0; mi < 4; mi++) {
#pragma unroll
            for (int ni = 0; ni < 4; ni++) {
                int lc = wn * 32 + ni * 8 + c0;
                float bb0 = cb[lc], bb1 = cb[lc + 1];
#pragma unroll
                for (int h = 0; h < 2; h++) {
                    int row = wm * 64 + mi * 16 + r0 + h * 8;
                    float* o = out + ((size_t)b * NL + row) * ND + n0 + lc;
                    float2 v = make_float2(acc[mi][ni][h * 2 + 0] + bb0,
                                           acc[mi][ni][h * 2 + 1] + bb1);
                    *(float2*)o = v;
                }
            }
        }
    }
}

// ---------------------------------------------------------------------------
extern "C" void kernel_launch(void* const* d_in, const int* in_sizes, int n_in,
                              void* d_out, int out_size) {
    const float* x      = (const float*)d_in[0];
    const float* logits = (const float*)d_in[1];
    const float* W1     = (const float*)d_in[2];
    const float* b1     = (const float*)d_in[3];
    const float* W2     = (const float*)d_in[4];
    const float* b2     = (const float*)d_in[5];
    const int*   masks  = (const int*)d_in[6];
    float* out = (float*)d_out;

    cudaFuncSetAttribute(gemm1_kernel, cudaFuncAttributeMaxDynamicSharedMemorySize, G1_SMEM);
    cudaFuncSetAttribute(gemm2_kernel, cudaFuncAttributeMaxDynamicSharedMemorySize, G2_SMEM);

    prep_kernel<<<PREP_GRID, 256>>>(x, W1, W2, logits, masks);
    gemm1_kernel<<<GRID_PERSIST, 256, G1_SMEM>>>(b1);
    gemm2_kernel<<<GRID_PERSIST, 256, G2_SMEM>>>(b2, out);
}

// round 11
// speedup vs baseline: 1.0387x; 1.0387x over previous
#include <cuda_runtime.h>
#include <cuda_fp16.h>
#include <math.h>
#include <stdint.h>

#define NB 512
#define NL 128
#define ND 256
#define NF 512
#define NE 8

// ---------------------------------------------------------------------------
// Device scratch (allocation-free rule)
// ---------------------------------------------------------------------------
__device__ float g_gates[NB * NE];
__device__ __half g_Xh[(size_t)NB * NL * ND];
__device__ __half g_W1T[(size_t)NE * NF * ND];   // [e][n][k]
__device__ __half g_W2T[(size_t)NE * ND * NF];   // [e][n][k]
__device__ __half g_H[(size_t)NB * NE * NL * NF];

// ---------------------------------------------------------------------------
// PTX helpers — baseline (non-'a') features only: cp.async, ldmatrix, mma.sync
// ---------------------------------------------------------------------------
__device__ __forceinline__ uint32_t smem_u32(const void* p) {
    uint32_t a;
    asm("{ .reg .u64 t; cvta.to.shared.u64 t, %1; cvt.u32.u64 %0, t; }" : "=r"(a) : "l"(p));
    return a;
}
__device__ __forceinline__ void cp16(uint32_t dst, const void* src) {
    asm volatile("cp.async.cg.shared.global [%0], [%1], 16;" :: "r"(dst), "l"(src));
}
#define CP_COMMIT() asm volatile("cp.async.commit_group;" ::: "memory")
#define CP_WAIT0()  asm volatile("cp.async.wait_group 0;" ::: "memory")
#define CP_WAIT1()  asm volatile("cp.async.wait_group 1;" ::: "memory")

#define LDSM4(r0, r1, r2, r3, addr) \
    asm volatile("ldmatrix.sync.aligned.m8n8.x4.shared.b16 {%0,%1,%2,%3}, [%4];" \
                 : "=r"(r0), "=r"(r1), "=r"(r2), "=r"(r3) : "r"(addr))

#define MMA16816(c, a, b0, b1) \
    asm volatile("mma.sync.aligned.m16n8k16.row.col.f32.f16.f16.f32 " \
                 "{%0,%1,%2,%3}, {%4,%5,%6,%7}, {%8,%9}, {%0,%1,%2,%3};" \
                 : "+f"((c)[0]), "+f"((c)[1]), "+f"((c)[2]), "+f"((c)[3]) \
                 : "r"((a)[0]), "r"((a)[1]), "r"((a)[2]), "r"((a)[3]), \
                   "r"(b0), "r"(b1))

__device__ __forceinline__ float gelu_exact(float v) {
    return 0.5f * v * (1.0f + erff(v * 0.70710678118654752f));
}

// ---------------------------------------------------------------------------
// Tile geometry
// ---------------------------------------------------------------------------
#define ROW_BYTES 144                               // streamed 64-col tiles
#define TILE_BYTES (128 * ROW_BYTES)                // 18432
// GEMM1 SMEM: X resident [128][264] f16 (stride 528B) + 2 B stages
#define X_STRIDE 528
#define G1_X 0
#define G1_B(st) (67584 + (st) * TILE_BYTES)
#define G1_SMEM (67584 + 2 * TILE_BYTES)            // 104448
// GEMM2 SMEM: 3 stages x (A+B)
#define STAGE_BYTES (2 * TILE_BYTES)                // 36864
#define SM_A(st) ((st) * STAGE_BYTES)
#define SM_B(st) ((st) * STAGE_BYTES + TILE_BYTES)
#define G2_SMEM (3 * STAGE_BYTES)                   // 110592

// Fill a [128 x 64] f16 tile (stride ROW_BYTES) via cp.async: 4 x 16B/thread.
__device__ __forceinline__ void fill_tile(uint32_t dst, const __half* src,
                                          int stride, int tid) {
#pragma unroll
    for (int i = 0; i < 4; i++) {
        int q = tid + i * 256;
        int r = q >> 3;
        int c = (q & 7) << 3;
        cp16(dst + r * ROW_BYTES + c * 2, src + (size_t)r * stride + c);
    }
}

// GEMM2-style compute: A and B both in streamed tiles.
__device__ __forceinline__ void compute_stage(uint32_t smb, int st, int wm, int wn,
                                              int lane, float acc[4][4][4]) {
#pragma unroll
    for (int ks = 0; ks < 4; ks++) {
        uint32_t a[4][4];
#pragma unroll
        for (int mi = 0; mi < 4; mi++) {
            uint32_t ad = smb + SM_A(st) +
                (wm * 64 + mi * 16 + (lane & 15)) * ROW_BYTES + ks * 32 + (lane >> 4) * 16;
            LDSM4(a[mi][0], a[mi][1], a[mi][2], a[mi][3], ad);
        }
        uint32_t bfr[2][4];
        int quad = lane >> 3;
#pragma unroll
        for (int g = 0; g < 2; g++) {
            uint32_t bd = smb + SM_B(st) +
                (wn * 32 + g * 16 + (quad >> 1) * 8 + (lane & 7)) * ROW_BYTES +
                ks * 32 + (quad & 1) * 16;
            LDSM4(bfr[g][0], bfr[g][1], bfr[g][2], bfr[g][3], bd);
        }
#pragma unroll
        for (int mi = 0; mi < 4; mi++)
#pragma unroll
            for (int ni = 0; ni < 4; ni++)
                MMA16816(acc[mi][ni], a[mi],
                         bfr[ni >> 1][(ni & 1) * 2], bfr[ni >> 1][(ni & 1) * 2 + 1]);
    }
}

// GEMM1 compute: A from resident X (stride 528B, chunk kc), B from streamed tile.
__device__ __forceinline__ void compute_xres(uint32_t smb, uint32_t bst, int kc,
                                             int wm, int wn, int lane,
                                             float acc[4][4][4]) {
#pragma unroll
    for (int ks = 0; ks < 4; ks++) {
        uint32_t a[4][4];
#pragma unroll
        for (int mi = 0; mi < 4; mi++) {
            uint32_t ad = smb + G1_X +
                (wm * 64 + mi * 16 + (lane & 15)) * X_STRIDE + kc * 128 + ks * 32 +
                (lane >> 4) * 16;
            LDSM4(a[mi][0], a[mi][1], a[mi][2], a[mi][3], ad);
        }
        uint32_t bfr[2][4];
        int quad = lane >> 3;
#pragma unroll
        for (int g = 0; g < 2; g++) {
            uint32_t bd = bst +
                (wn * 32 + g * 16 + (quad >> 1) * 8 + (lane & 7)) * ROW_BYTES +
                ks * 32 + (quad & 1) * 16;
            LDSM4(bfr[g][0], bfr[g][1], bfr[g][2], bfr[g][3], bd);
        }
#pragma unroll
        for (int mi = 0; mi < 4; mi++)
#pragma unroll
            for (int ni = 0; ni < 4; ni++)
                MMA16816(acc[mi][ni], a[mi],
                         bfr[ni >> 1][(ni & 1) * 2], bfr[ni >> 1][(ni & 1) * 2 + 1]);
    }
}

// ---------------------------------------------------------------------------
// Merged prep kernel: gates + X convert + W1/W2 transposes.
// Grid layout: [0, 8192)            prep_x (8 f32->f16 per thread)
//              [8192, 9216)         prep_w1 tiles (16 x 8 x 8)
//              [9216, 10240)        prep_w2 tiles (8 x 16 x 8)
//              [10240, 10242)       gates
// ---------------------------------------------------------------------------
#define PREP_GRID 10242

__global__ void prep_kernel(const float* __restrict__ x,
                            const float* __restrict__ W1,
                            const float* __restrict__ W2,
                            const float* __restrict__ logits,
                            const int* __restrict__ masks) {
    __shared__ float t[32][33];
    const int bid = blockIdx.x;
    if (bid < 8192) {
        size_t i0 = ((size_t)bid * 256 + threadIdx.x) * 8;
        float4 v0 = *(const float4*)(x + i0);
        float4 v1 = *(const float4*)(x + i0 + 4);
        __half2 h0 = __floats2half2_rn(v0.x, v0.y);
        __half2 h1 = __floats2half2_rn(v0.z, v0.w);
        __half2 h2 = __floats2half2_rn(v1.x, v1.y);
        __half2 h3 = __floats2half2_rn(v1.z, v1.w);
        uint4 u;
        u.x = *(uint32_t*)&h0; u.y = *(uint32_t*)&h1;
        u.z = *(uint32_t*)&h2; u.w = *(uint32_t*)&h3;
        *(uint4*)(g_Xh + i0) = u;
    } else if (bid < 9216) {
        int id = bid - 8192;                 // nt(16) x kt(8) x e(8)
        int nt = id & 15, kt = (id >> 4) & 7, e = id >> 7;
        int k0 = kt * 32, n0 = nt * 32;
        int r = threadIdx.x >> 5, c = threadIdx.x & 31;
#pragma unroll
        for (int i = 0; i < 4; i++)
            t[r + i * 8][c] = W1[((size_t)e * ND + k0 + r + i * 8) * NF + n0 + c];
        __syncthreads();
#pragma unroll
        for (int i = 0; i < 4; i++)
            g_W1T[((size_t)e * NF + n0 + r + i * 8) * ND + k0 + c] =
                __float2half(t[c][r + i * 8]);
    } else if (bid < 10240) {
        int id = bid - 9216;                 // nt(8) x kt(16) x e(8)
        int nt = id & 7, kt = (id >> 3) & 15, e = id >> 7;
        int k0 = kt * 32, n0 = nt * 32;
        int r = threadIdx.x >> 5, c = threadIdx.x & 31;
#pragma unroll
        for (int i = 0; i < 4; i++)
            t[r + i * 8][c] = W2[((size_t)e * NF + k0 + r + i * 8) * ND + n0 + c];
        __syncthreads();
#pragma unroll
        for (int i = 0; i < 4; i++)
            g_W2T[((size_t)e * ND + n0 + r + i * 8) * NF + k0 + c] =
                __float2half(t[c][r + i * 8]);
    } else {
        int b = (bid - 10240) * 256 + threadIdx.x;
        if (b >= NB) return;
        float v[NE]; float mx = -1e30f;
#pragma unroll
        for (int e = 0; e < NE; e++) { v[e] = logits[b * NE + e]; mx = fmaxf(mx, v[e]); }
        float s = 0.f;
#pragma unroll
        for (int e = 0; e < NE; e++) { v[e] = expf(v[e] - mx); s += v[e]; }
        float inv = 1.f / s; float gs = 0.f;
#pragma unroll
        for (int e = 0; e < NE; e++) {
            v[e] = (masks[b * NE + e] == 1) ? v[e] * inv : 0.f;
            gs += v[e];
        }
        float d = 1.f / (gs + 1e-9f);
#pragma unroll
        for (int e = 0; e < NE; e++) g_gates[b * NE + e] = v[e] * d;
    }
}

// ---------------------------------------------------------------------------
// GEMM1: one CTA per active (b, e). X resident in SMEM; W1 B-tiles streamed
// (2-stage, 18KB/chunk). For nt in 0..3: K=256 loop, epilogue
// H = gate*gelu(D + b1) -> fp16, SMEM-staged coalesced stores.
// ---------------------------------------------------------------------------
__global__ void __launch_bounds__(256, 2) gemm1_kernel(const float* __restrict__ b1) {
    const int b = blockIdx.x, e = blockIdx.y;
    const float gate = g_gates[b * NE + e];
    if (gate == 0.0f) return;

    extern __shared__ __align__(128) char sm[];
    const uint32_t smb = smem_u32(sm);
    const int tid = threadIdx.x, lane = tid & 31, wid = tid >> 5;
    const int wm = wid & 1, wn = wid >> 1;

    // Load X[b] (128 x 256 f16) into resident SMEM.
    {
        const __half* Xs = g_Xh + (size_t)b * NL * ND;
#pragma unroll
        for (int i = 0; i < 16; i++) {
            int q = tid + i * 256;          // 128 rows x 32 16B-chunks
            int r = q >> 5;
            int c = (q & 31) << 3;
            cp16(smb + G1_X + r * X_STRIDE + c * 2, Xs + (size_t)r * ND + c);
        }
        CP_COMMIT();
    }

    const __half* Bbase = g_W1T + (size_t)e * NF * ND;

    for (int nt = 0; nt < 4; nt++) {
        const __half* Bt = Bbase + (size_t)(nt * 128) * ND;
        fill_tile(G1_B(0) + smb, Bt, ND, tid); CP_COMMIT();
        fill_tile(G1_B(1) + smb, Bt + 64, ND, tid); CP_COMMIT();

        float acc[4][4][4] = {};
#pragma unroll
        for (int kc = 0; kc < 4; kc++) {
            if (kc < 3) { CP_WAIT1(); } else { CP_WAIT0(); }
            __syncthreads();
            compute_xres(smb, smb + G1_B(kc & 1), kc, wm, wn, lane, acc);
            __syncthreads();
            if (kc + 2 < 4) {
                fill_tile(G1_B(kc & 1) + smb, Bt + (kc + 2) * 64, ND, tid);
                CP_COMMIT();
            }
        }

        // Epilogue: stage gated-GELU fp16 tile (stride 272B) in B area, then
        // coalesced 16B global writes.
        const uint32_t sh = smb + G1_B(0);
        const int r0 = lane >> 2, c0 = (lane & 3) * 2;
#pragma unroll
        for (int mi = 0; mi < 4; mi++) {
#pragma unroll
            for (int ni = 0; ni < 4; ni++) {
                int lc = wn * 32 + ni * 8 + c0;
                float bb0 = __ldg(b1 + e * NF + nt * 128 + lc);
                float bb1 = __ldg(b1 + e * NF + nt * 128 + lc + 1);
#pragma unroll
                for (int h = 0; h < 2; h++) {
                    int row = wm * 64 + mi * 16 + r0 + h * 8;
                    float v0 = gate * gelu_exact(acc[mi][ni][h * 2 + 0] + bb0);
                    float v1 = gate * gelu_exact(acc[mi][ni][h * 2 + 1] + bb1);
                    __half h0 = __float2half(v0);
                    __half h1 = __float2half(v1);
                    uint32_t hp = (uint32_t)__half_as_ushort(h0) |
                                  ((uint32_t)__half_as_ushort(h1) << 16);
                    asm volatile("st.shared.b32 [%0], %1;"
                                 :: "r"(sh + row * 272 + lc * 2), "r"(hp));
                }
            }
        }
        __syncthreads();

        __half* Hp = g_H + (size_t)(b * NE + e) * NL * NF + nt * 128;
#pragma unroll
        for (int it = 0; it < 8; it++) {
            int idx = tid + it * 256;       // 128 rows x 16 16B-units
            int row = idx >> 4;
            int u = idx & 15;
            float4 vh;
            asm volatile("ld.shared.v4.b32 {%0,%1,%2,%3}, [%4];"
                         : "=f"(vh.x), "=f"(vh.y), "=f"(vh.z), "=f"(vh.w)
                         : "r"(sh + row * 272 + u * 16));
            *(float4*)(Hp + (size_t)row * NF + u * 8) = vh;
        }
        __syncthreads();   // staging buffer reused by next nt's fills
    }
}

// ---------------------------------------------------------------------------
// GEMM2: per (nt, b): out = sum_{e active} H_e[128,512] @ W2T_e[.,512]^T
//        + sum_e g_e * b2_e.  Grid is (nt, b) so the two tiles sharing the
// same H[b] stream are ADJACENT blockIdx values -> nearby SMs, L2-shared H.
// 3-stage pipeline, one barrier per chunk (head barrier orders WAR).
// ---------------------------------------------------------------------------
__global__ void __launch_bounds__(256, 2) gemm2_kernel(const float* __restrict__ b2,
                                                       float* __restrict__ out) {
    const int nt = blockIdx.x, b = blockIdx.y;
    const int tid = threadIdx.x, lane = tid & 31, wid = tid >> 5;
    const int wm = wid & 1, wn = wid >> 1;
    const int n0 = nt * 128;

    float gates[NE];
    int act[NE], na = 0;
#pragma unroll
    for (int e = 0; e < NE; e++) {
        gates[e] = g_gates[b * NE + e];
        if (gates[e] != 0.0f) act[na++] = e;
    }
    if (na == 0) {
        float4 z = make_float4(0.f, 0.f, 0.f, 0.f);
        float* o = out + (size_t)b * NL * ND + n0;
        for (int i = tid; i < NL * 32; i += 256) {
            int r = i >> 5, c = (i & 31) << 2;
            *(float4*)(o + (size_t)r * ND + c) = z;
        }
        return;
    }

    extern __shared__ __align__(128) char sm[];
    __shared__ float cb[128];
    const uint32_t smb = smem_u32(sm);

    if (tid < 128) {
        float s = 0.f;
#pragma unroll
        for (int e = 0; e < NE; e++) s += gates[e] * __ldg(b2 + e * ND + n0 + tid);
        cb[tid] = s;
    }

    float acc[4][4][4] = {};
    const int total = na * 8;  // per expert: 8 BK=64 chunks over K=512

    auto srcs = [&](int i, const __half*& As, const __half*& Bs) {
        int e = act[i >> 3];
        int k = (i & 7) << 6;
        As = g_H + (size_t)(b * NE + e) * NL * NF + k;
        Bs = g_W2T + ((size_t)e * ND + n0) * NF + k;
    };

    {
        const __half *As, *Bs;
        srcs(0, As, Bs);
        fill_tile(smb + SM_A(0), As, NF, tid);
        fill_tile(smb + SM_B(0), Bs, NF, tid);
        CP_COMMIT();
        srcs(1, As, Bs);
        fill_tile(smb + SM_A(1), As, NF, tid);
        fill_tile(smb + SM_B(1), Bs, NF, tid);
        CP_COMMIT();
    }
    for (int i = 0; i < total; i++) {
        if (i + 1 < total) { CP_WAIT1(); } else { CP_WAIT0(); }
        __syncthreads();                     // single barrier per chunk
        if (i + 2 < total) {
            const __half *As, *Bs;
            srcs(i + 2, As, Bs);
            fill_tile(smb + SM_A((i + 2) % 3), As, NF, tid);
            fill_tile(smb + SM_B((i + 2) % 3), Bs, NF, tid);
            CP_COMMIT();
        }
        compute_stage(smb, i % 3, wm, wn, lane, acc);
    }

    // Epilogue: add gate-weighted bias, write fp32 out
    const int r0 = lane >> 2, c0 = (lane & 3) * 2;
#pragma unroll
    for (int mi = 0; mi < 4; mi++) {
#pragma unroll
        for (int ni = 0; ni < 4; ni++) {
            int lc = wn * 32 + ni * 8 + c0;
            float bb0 = cb[lc], bb1 = cb[lc + 1];
#pragma unroll
            for (int h = 0; h < 2; h++) {
                int row = wm * 64 + mi * 16 + r0 + h * 8;
                float* o = out + ((size_t)b * NL + row) * ND + n0 + lc;
                float2 v = make_float2(acc[mi][ni][h * 2 + 0] + bb0,
                                       acc[mi][ni][h * 2 + 1] + bb1);
                *(float2*)o = v;
            }
        }
    }
}

// ---------------------------------------------------------------------------
extern "C" void kernel_launch(void* const* d_in, const int* in_sizes, int n_in,
                              void* d_out, int out_size) {
    const float* x      = (const float*)d_in[0];
    const float* logits = (const float*)d_in[1];
    const float* W1     = (const float*)d_in[2];
    const float* b1     = (const float*)d_in[3];
    const float* W2     = (const float*)d_in[4];
    const float* b2     = (const float*)d_in[5];
    const int*   masks  = (const int*)d_in[6];
    float* out = (float*)d_out;

    cudaFuncSetAttribute(gemm1_kernel, cudaFuncAttributeMaxDynamicSharedMemorySize, G1_SMEM);
    cudaFuncSetAttribute(gemm2_kernel, cudaFuncAttributeMaxDynamicSharedMemorySize, G2_SMEM);

    prep_kernel<<<PREP_GRID, 256>>>(x, W1, W2, logits, masks);
    gemm1_kernel<<<dim3(NB, NE), 256, G1_SMEM>>>(b1);
    gemm2_kernel<<<dim3(ND / 128, NB), 256, G2_SMEM>>>(b2, out);
}